// round 16
// baseline (speedup 1.0000x reference)
#include <cuda_runtime.h>
#include <cuda_fp16.h>
#include <math.h>
#include <stdint.h>

// Problem constants
#define BB      4
#define TT      1024
#define DMODEL  2048
#define NHEADS  16
#define HDIM    128
#define MTOK    (BB * TT)        // 4096
#define NQKV    (3 * DMODEL)     // 6144
#define GK      2048

// ---------------------------------------------------------------------------
// Scratch (device globals)
// ---------------------------------------------------------------------------
__device__ __half g_xf[(size_t)MTOK * DMODEL];
__device__ __half g_wqt[(size_t)NQKV * DMODEL];    // w_qkv^T [6144,2048]
__device__ __half g_wot[(size_t)DMODEL * DMODEL];  // w_out^T [2048,2048]
__device__ __half g_qkvf[(size_t)MTOK * NQKV];
__device__ __half g_atf[(size_t)MTOK * DMODEL];

// ---------------------------------------------------------------------------
// PTX helpers (sm_80-class only: legal on plain compute_103)
// ---------------------------------------------------------------------------
__device__ __forceinline__ uint32_t smem_u32(const void* p) {
    uint32_t a;
    asm("{ .reg .u64 t; cvta.to.shared.u64 t, %1; cvt.u32.u64 %0, t; }" : "=r"(a) : "l"(p));
    return a;
}
__device__ __forceinline__ void cp16(uint32_t dst, const void* src) {
    asm volatile("cp.async.cg.shared.global [%0], [%1], 16;"
                 :: "r"(dst), "l"(__cvta_generic_to_global(src)) : "memory");
}
__device__ __forceinline__ void cp_commit() { asm volatile("cp.async.commit_group;" ::: "memory"); }
__device__ __forceinline__ void cp_wait0()  { asm volatile("cp.async.wait_group 0;" ::: "memory"); }
__device__ __forceinline__ void cp_wait1()  { asm volatile("cp.async.wait_group 1;" ::: "memory"); }

__device__ __forceinline__ void ldsm4(uint32_t (&r)[4], uint32_t addr) {
    asm volatile("ldmatrix.sync.aligned.m8n8.x4.shared.b16 {%0,%1,%2,%3}, [%4];"
                 : "=r"(r[0]), "=r"(r[1]), "=r"(r[2]), "=r"(r[3]) : "r"(addr));
}
__device__ __forceinline__ void ldsm4t(uint32_t (&r)[4], uint32_t addr) {
    asm volatile("ldmatrix.sync.aligned.m8n8.x4.trans.shared.b16 {%0,%1,%2,%3}, [%4];"
                 : "=r"(r[0]), "=r"(r[1]), "=r"(r[2]), "=r"(r[3]) : "r"(addr));
}
__device__ __forceinline__ void mma16816(float (&d)[4], const uint32_t (&a)[4],
                                         uint32_t b0, uint32_t b1) {
    asm volatile("mma.sync.aligned.m16n8k16.row.col.f32.f16.f16.f32 "
                 "{%0,%1,%2,%3}, {%4,%5,%6,%7}, {%8,%9}, {%0,%1,%2,%3};"
                 : "+f"(d[0]), "+f"(d[1]), "+f"(d[2]), "+f"(d[3])
                 : "r"(a[0]), "r"(a[1]), "r"(a[2]), "r"(a[3]), "r"(b0), "r"(b1));
}
__device__ __forceinline__ uint32_t pack_h2(float x, float y) {
    __half2 h = __floats2half2_rn(x, y);
    return *reinterpret_cast<uint32_t*>(&h);
}

// ---------------------------------------------------------------------------
// Convert fp32 -> fp16
// ---------------------------------------------------------------------------
__global__ void convert_kernel(const float* __restrict__ in,
                               __half* __restrict__ outp, int n4)
{
    int i = blockIdx.x * blockDim.x + threadIdx.x;
    if (i >= n4) return;
    float4 v = ((const float4*)in)[i];
    uint2 o;
    o.x = pack_h2(v.x, v.y);
    o.y = pack_h2(v.z, v.w);
    ((uint2*)outp)[i] = o;
}

// ---------------------------------------------------------------------------
// Transpose + convert: W [K,N] fp32 -> Wt [N,K] fp16
// ---------------------------------------------------------------------------
__global__ void transpose_convert_kernel(const float* __restrict__ W,
                                         __half* __restrict__ Tt,
                                         int K, int N)
{
    __shared__ float t[32][33];
    const int tx = threadIdx.x, ty = threadIdx.y;
    const int n0 = blockIdx.x * 32, k0 = blockIdx.y * 32;
    #pragma unroll
    for (int i = 0; i < 4; ++i)
        t[ty + 8 * i][tx] = W[(size_t)(k0 + ty + 8 * i) * N + n0 + tx];
    __syncthreads();
    #pragma unroll
    for (int i = 0; i < 4; ++i) {
        float v = t[tx][ty + 8 * i];
        Tt[(size_t)(n0 + ty + 8 * i) * K + k0 + tx] = __float2half_rn(v);
    }
}

// ---------------------------------------------------------------------------
// fp16 GEMM via mma.sync: C[M,N] = A@B^T + bias.  (R15 configuration —
// measured best; unchanged.)
// ---------------------------------------------------------------------------
#define BKG       64
#define NCHUNK    (GK / BKG)      // 32
#define STAGES    3
#define A_OFF     0               // 128 rows x 128B = 16384
#define B_OFF     16384
#define STAGE_BYTES 32768
#define GSMEM     (STAGES * STAGE_BYTES)   // 98304

__device__ __forceinline__ uint32_t swg(int r, int s) {
    return (uint32_t)(r * 128 + ((s ^ (r & 7)) << 4));
}

__device__ __forceinline__ void load_stage(uint32_t sb, int stage,
                                           const __half* __restrict__ A,
                                           const __half* __restrict__ B,
                                           int brow, int bcol, int k0, int tid)
{
    const uint32_t base = sb + (uint32_t)stage * STAGE_BYTES;
    const int r = tid >> 1;               // 0..127
    const int sbase = (tid & 1) << 2;     // 0 or 4
    const __half* a = A + (size_t)(brow + r) * GK + k0 + sbase * 8;
    const __half* b = B + (size_t)(bcol + r) * GK + k0 + sbase * 8;
    #pragma unroll
    for (int i = 0; i < 4; ++i) {
        const uint32_t o = swg(r, sbase + i);
        cp16(base + A_OFF + o, a + i * 8);
        cp16(base + B_OFF + o, b + i * 8);
    }
    cp_commit();
}

template <bool HALF_OUT>
__global__ __launch_bounds__(256, 2)
void gemm_f16_kernel(const __half* __restrict__ A,
                     const __half* __restrict__ B,
                     const float* __restrict__ bias,
                     float* __restrict__ C,
                     __half* __restrict__ Ch, int N)
{
    extern __shared__ char smem[];
    const uint32_t sb = smem_u32(smem);
    const int tid  = threadIdx.x;
    const int lane = tid & 31;
    const int wid  = tid >> 5;
    const int wm   = wid >> 1;
    const int wn   = wid & 1;
    const int brow = blockIdx.y * 128;
    const int bcol = blockIdx.x * 128;
    const int m0   = wm * 32;
    const int n0   = wn * 64;
    const int kk0  = (wid & 1) << 1;     // phase stagger: 0 or 2

    float acc[2][8][4];
    #pragma unroll
    for (int mt = 0; mt < 2; ++mt)
        #pragma unroll
        for (int nt = 0; nt < 8; ++nt)
            #pragma unroll
            for (int i = 0; i < 4; ++i) acc[mt][nt][i] = 0.0f;

    load_stage(sb, 0, A, B, brow, bcol, 0, tid);
    load_stage(sb, 1, A, B, brow, bcol, BKG, tid);

    #pragma unroll 2
    for (int c = 0; c < NCHUNK; ++c) {
        if (c + 1 < NCHUNK) cp_wait1(); else cp_wait0();
        __syncthreads();
        if (c + 2 < NCHUNK)
            load_stage(sb, (c + 2) % STAGES, A, B, brow, bcol,
                       (c + 2) * BKG, tid);

        const uint32_t st = sb + (uint32_t)(c % STAGES) * STAGE_BYTES;
        #pragma unroll
        for (int kx = 0; kx < 4; ++kx) {     // staggered k16 steps in BK=64
            const int kk = (kx + kk0) & 3;
            uint32_t aF[2][4], bF[4][4];
            const int seg = 2 * kk + (lane >> 4);
            #pragma unroll
            for (int mt = 0; mt < 2; ++mt)
                ldsm4(aF[mt], st + A_OFF + swg(m0 + mt * 16 + (lane & 15), seg));
            #pragma unroll
            for (int p = 0; p < 4; ++p)
                ldsm4(bF[p], st + B_OFF + swg(n0 + p * 16 + (lane & 15), seg));
            #pragma unroll
            for (int mt = 0; mt < 2; ++mt)
                #pragma unroll
                for (int nt = 0; nt < 8; ++nt) {
                    const int p = nt >> 1, sub = nt & 1;
                    mma16816(acc[mt][nt], aF[mt], bF[p][sub], bF[p][sub + 2]);
                }
        }
        // no end-of-chunk barrier: next iteration's top barrier (after
        // cp_wait) orders all reads of this stage before its rewrite.
    }

    #pragma unroll
    for (int mt = 0; mt < 2; ++mt) {
        const int r0 = brow + m0 + mt * 16 + (lane >> 2);
        #pragma unroll
        for (int nt = 0; nt < 8; ++nt) {
            const int col = bcol + n0 + nt * 8 + (lane & 3) * 2;
            const float b0 = bias[col], b1 = bias[col + 1];
            const float v0 = acc[mt][nt][0] + b0, v1 = acc[mt][nt][1] + b1;
            const float v2 = acc[mt][nt][2] + b0, v3 = acc[mt][nt][3] + b1;
            if (HALF_OUT) {
                *(uint32_t*)(Ch + (size_t)r0 * N + col) = pack_h2(v0, v1);
                *(uint32_t*)(Ch + (size_t)(r0 + 8) * N + col) = pack_h2(v2, v3);
            } else {
                *(float2*)(C + (size_t)r0 * N + col) = make_float2(v0, v1);
                *(float2*)(C + (size_t)(r0 + 8) * N + col) = make_float2(v2, v3);
            }
        }
    }
}

// ---------------------------------------------------------------------------
// Flash attention via mma.sync (fp16 single-term), causal — now with the
// GEMM's 3-stage KV ring: depth-2 prefetch, ONE barrier per iteration
// (the next iteration's top barrier protects stage reuse; no bottom barrier).
// Smem: Q 32KB + 3 x 32KB KV stages = 128KB, 1 CTA/SM (unchanged residency).
// ---------------------------------------------------------------------------
#define FBQ   128
#define FBKV  64
#define FQ_O  0
#define FSTG  32768
#define FSTGSZ 32768
#define FSTAGES 3
#define FK_O  0
#define FV_O  16384
#define FSMEM (FSTG + FSTAGES * FSTGSZ)   // 131072

__device__ __forceinline__ uint32_t swzf(int r, int c) {
    return (uint32_t)(r * 256 + ((c ^ (r & 7)) << 4));
}

__device__ __forceinline__ void load_kv(uint32_t sb, int stage,
                                        const __half* __restrict__ qkvf,
                                        int b, int jj, int h, int tid)
{
    const uint32_t stb = sb + FSTG + (uint32_t)stage * FSTGSZ;
    #pragma unroll
    for (int i = 0; i < 4; ++i) {
        const int idx = i * 256 + tid;
        const int r = idx >> 4, c = idx & 15;
        const uint32_t o = swzf(r, c);
        const size_t gk = (size_t)(b * TT + jj * FBKV + r) * NQKV
                        + DMODEL + h * HDIM + c * 8;
        cp16(stb + FK_O + o, qkvf + gk);
        cp16(stb + FV_O + o, qkvf + gk + DMODEL);
    }
    cp_commit();
}

__global__ __launch_bounds__(256)
void flash_mma_kernel(const __half* __restrict__ qkvf,
                      __half* __restrict__ of)
{
    extern __shared__ char smem[];
    const uint32_t sb = smem_u32(smem);
    const int tid  = threadIdx.x;
    const int lane = tid & 31;
    const int wid  = tid >> 5;
    const int qb   = blockIdx.x;
    const int bh   = blockIdx.y;
    const int b    = bh >> 4;
    const int h    = bh & 15;
    const int m0   = wid * 16;
    const int tokQ = b * TT + qb * FBQ;
    const float scale = 0.08838834764831845f;
    const int jmax = 2 * qb + 1;   // >= 1, so >= 2 iterations always

    // Prologue: group0 = Q + KV(0); group1 = KV(1)
    {
        #pragma unroll
        for (int i = 0; i < 8; ++i) {
            const int idx = i * 256 + tid;
            const int r = idx >> 4, c = idx & 15;
            cp16(sb + FQ_O + swzf(r, c),
                 qkvf + (size_t)(tokQ + r) * NQKV + h * HDIM + c * 8);
        }
        #pragma unroll
        for (int i = 0; i < 4; ++i) {
            const int idx = i * 256 + tid;
            const int r = idx >> 4, c = idx & 15;
            const uint32_t o = swzf(r, c);
            const size_t gk = (size_t)(b * TT + r) * NQKV + DMODEL + h * HDIM + c * 8;
            cp16(sb + FSTG + FK_O + o, qkvf + gk);
            cp16(sb + FSTG + FV_O + o, qkvf + gk + DMODEL);
        }
        cp_commit();
    }
    load_kv(sb, 1, qkvf, b, 1, h, tid);

    float m_[2] = {-1e30f, -1e30f};
    float l_[2] = {0.0f, 0.0f};
    float o_[16][4];
    #pragma unroll
    for (int ng = 0; ng < 16; ++ng)
        #pragma unroll
        for (int i = 0; i < 4; ++i) o_[ng][i] = 0.0f;

    uint32_t qF[8][4];
    const int qrow0 = qb * FBQ + m0 + (lane >> 2);

    for (int j = 0; j <= jmax; ++j) {
        if (j < jmax) cp_wait1(); else cp_wait0();
        __syncthreads();
        if (j + 2 <= jmax)
            load_kv(sb, (j + 2) % FSTAGES, qkvf, b, j + 2, h, tid);

        if (j == 0) {   // Q data ready (group 0): load fragments once
            #pragma unroll
            for (int kc = 0; kc < 8; ++kc)
                ldsm4(qF[kc], sb + FQ_O + swzf(m0 + (lane & 15), 2 * kc + (lane >> 4)));
        }

        const uint32_t st = sb + FSTG + (uint32_t)(j % FSTAGES) * FSTGSZ;

        float s[8][4];
        #pragma unroll
        for (int nt = 0; nt < 8; ++nt)
            #pragma unroll
            for (int i = 0; i < 4; ++i) s[nt][i] = 0.0f;

        #pragma unroll
        for (int kc = 0; kc < 8; ++kc) {
            #pragma unroll
            for (int p = 0; p < 4; ++p) {
                uint32_t kF[4];
                ldsm4(kF, st + FK_O + swzf(p * 16 + (lane & 15), 2 * kc + (lane >> 4)));
                #pragma unroll
                for (int sub = 0; sub < 2; ++sub)
                    mma16816(s[2 * p + sub], qF[kc], kF[sub], kF[sub + 2]);
            }
        }

        #pragma unroll
        for (int nt = 0; nt < 8; ++nt)
            #pragma unroll
            for (int i = 0; i < 4; ++i) s[nt][i] *= scale;
        if (j >= 2 * qb) {
            const int kb = j * FBKV + ((lane & 3) << 1);
            #pragma unroll
            for (int nt = 0; nt < 8; ++nt) {
                const int k0 = kb + nt * 8, k1 = k0 + 1;
                if (k0 > qrow0)     s[nt][0] = -1e30f;
                if (k1 > qrow0)     s[nt][1] = -1e30f;
                if (k0 > qrow0 + 8) s[nt][2] = -1e30f;
                if (k1 > qrow0 + 8) s[nt][3] = -1e30f;
            }
        }

        float mx0 = -1e30f, mx1 = -1e30f;
        #pragma unroll
        for (int nt = 0; nt < 8; ++nt) {
            mx0 = fmaxf(mx0, fmaxf(s[nt][0], s[nt][1]));
            mx1 = fmaxf(mx1, fmaxf(s[nt][2], s[nt][3]));
        }
        mx0 = fmaxf(mx0, __shfl_xor_sync(0xffffffffu, mx0, 1));
        mx0 = fmaxf(mx0, __shfl_xor_sync(0xffffffffu, mx0, 2));
        mx1 = fmaxf(mx1, __shfl_xor_sync(0xffffffffu, mx1, 1));
        mx1 = fmaxf(mx1, __shfl_xor_sync(0xffffffffu, mx1, 2));
        const float mn0 = fmaxf(m_[0], mx0);
        const float mn1 = fmaxf(m_[1], mx1);
        const float a0 = __expf(m_[0] - mn0);
        const float a1 = __expf(m_[1] - mn1);
        float sum0 = 0.0f, sum1 = 0.0f;
        #pragma unroll
        for (int nt = 0; nt < 8; ++nt) {
            s[nt][0] = __expf(s[nt][0] - mn0); sum0 += s[nt][0];
            s[nt][1] = __expf(s[nt][1] - mn0); sum0 += s[nt][1];
            s[nt][2] = __expf(s[nt][2] - mn1); sum1 += s[nt][2];
            s[nt][3] = __expf(s[nt][3] - mn1); sum1 += s[nt][3];
        }
        sum0 += __shfl_xor_sync(0xffffffffu, sum0, 1);
        sum0 += __shfl_xor_sync(0xffffffffu, sum0, 2);
        sum1 += __shfl_xor_sync(0xffffffffu, sum1, 1);
        sum1 += __shfl_xor_sync(0xffffffffu, sum1, 2);
        l_[0] = l_[0] * a0 + sum0;
        l_[1] = l_[1] * a1 + sum1;
        m_[0] = mn0; m_[1] = mn1;
        #pragma unroll
        for (int ng = 0; ng < 16; ++ng) {
            o_[ng][0] *= a0; o_[ng][1] *= a0;
            o_[ng][2] *= a1; o_[ng][3] *= a1;
        }

        // O += P V
        #pragma unroll
        for (int kt = 0; kt < 4; ++kt) {
            uint32_t pF[4];
            pF[0] = pack_h2(s[2 * kt][0],     s[2 * kt][1]);
            pF[1] = pack_h2(s[2 * kt][2],     s[2 * kt][3]);
            pF[2] = pack_h2(s[2 * kt + 1][0], s[2 * kt + 1][1]);
            pF[3] = pack_h2(s[2 * kt + 1][2], s[2 * kt + 1][3]);
            #pragma unroll
            for (int g2 = 0; g2 < 8; ++g2) {
                uint32_t vF[4];
                ldsm4t(vF, st + FV_O + swzf(kt * 16 + (lane & 15), 2 * g2 + (lane >> 4)));
                #pragma unroll
                for (int sub = 0; sub < 2; ++sub)
                    mma16816(o_[2 * g2 + sub], pF, vF[2 * sub], vF[2 * sub + 1]);
            }
        }
        // no end-of-loop barrier: 3-stage ring + next iteration's top barrier
        // protects stage reuse (stage (j+2)%3 was last read in iter j-1).
    }

    const float inv0 = 1.0f / l_[0];
    const float inv1 = 1.0f / l_[1];
    const size_t tok0 = (size_t)tokQ + m0 + (lane >> 2);
    #pragma unroll
    for (int ng = 0; ng < 16; ++ng) {
        const int col = h * HDIM + ng * 8 + ((lane & 3) << 1);
        *(uint32_t*)(of + tok0 * DMODEL + col) =
            pack_h2(o_[ng][0] * inv0, o_[ng][1] * inv0);
        *(uint32_t*)(of + (tok0 + 8) * DMODEL + col) =
            pack_h2(o_[ng][2] * inv1, o_[ng][3] * inv1);
    }
}

// ---------------------------------------------------------------------------
extern "C" void kernel_launch(void* const* d_in, const int* in_sizes, int n_in,
                              void* d_out, int out_size)
{
    (void)in_sizes; (void)n_in; (void)out_size;
    const float* x      = (const float*)d_in[0];
    const float* w_qkv  = (const float*)d_in[1];
    const float* b_qkv  = (const float*)d_in[2];
    const float* w_out  = (const float*)d_in[3];
    const float* b_out  = (const float*)d_in[4];
    float* out          = (float*)d_out;

    void *xf, *wq, *wo, *qvf, *atf;
    cudaGetSymbolAddress(&xf, g_xf);
    cudaGetSymbolAddress(&wq, g_wqt);
    cudaGetSymbolAddress(&wo, g_wot);
    cudaGetSymbolAddress(&qvf, g_qkvf);
    cudaGetSymbolAddress(&atf, g_atf);

    cudaFuncSetAttribute(gemm_f16_kernel<true>,
                         cudaFuncAttributeMaxDynamicSharedMemorySize, GSMEM);
    cudaFuncSetAttribute(gemm_f16_kernel<false>,
                         cudaFuncAttributeMaxDynamicSharedMemorySize, GSMEM);
    cudaFuncSetAttribute(flash_mma_kernel,
                         cudaFuncAttributeMaxDynamicSharedMemorySize, FSMEM);

    // Side streams + events for prep overlap (created once; capture-fork idiom)
    static cudaStream_t s1 = nullptr, s2 = nullptr;
    static cudaEvent_t eFork = nullptr, eWq = nullptr, eWo = nullptr;
    if (!s1) {
        cudaStreamCreateWithFlags(&s1, cudaStreamNonBlocking);
        cudaStreamCreateWithFlags(&s2, cudaStreamNonBlocking);
        cudaEventCreateWithFlags(&eFork, cudaEventDisableTiming);
        cudaEventCreateWithFlags(&eWq, cudaEventDisableTiming);
        cudaEventCreateWithFlags(&eWo, cudaEventDisableTiming);
    }

    // Fork: s1 (w_qkv transpose) and s2 (w_out transpose) branch off main
    cudaEventRecord(eFork, 0);
    cudaStreamWaitEvent(s1, eFork, 0);
    cudaStreamWaitEvent(s2, eFork, 0);

    {
        dim3 blk(32, 8);
        transpose_convert_kernel<<<dim3(NQKV / 32, DMODEL / 32), blk, 0, s1>>>(
            w_qkv, (__half*)wq, DMODEL, NQKV);
        cudaEventRecord(eWq, s1);
        transpose_convert_kernel<<<dim3(DMODEL / 32, DMODEL / 32), blk, 0, s2>>>(
            w_out, (__half*)wo, DMODEL, DMODEL);
        cudaEventRecord(eWo, s2);
    }
    // Convert x on main stream (overlaps with both transposes)
    {
        const int n4 = MTOK * DMODEL / 4;
        convert_kernel<<<(n4 + 255) / 256, 256>>>(x, (__half*)xf, n4);
    }

    // 1) QKV projection -> fp16 (needs xf + wqt)
    cudaStreamWaitEvent(0, eWq, 0);
    {
        dim3 grid(NQKV / 128, MTOK / 128);
        gemm_f16_kernel<true><<<grid, 256, GSMEM>>>(
            (const __half*)xf, (const __half*)wq, b_qkv,
            nullptr, (__half*)qvf, NQKV);
    }
    // 2) Causal flash attention -> fp16 (w_out transpose overlaps all of this)
    {
        dim3 grid(TT / FBQ, BB * NHEADS);
        flash_mma_kernel<<<grid, 256, FSMEM>>>(
            (const __half*)qvf, (__half*)atf);
    }
    // 3) Output projection -> fp32 out (needs atf + wot)
    cudaStreamWaitEvent(0, eWo, 0);
    {
        dim3 grid(DMODEL / 128, MTOK / 128);
        gemm_f16_kernel<false><<<grid, 256, GSMEM>>>(
            (const __half*)atf, (const __half*)wo, b_out,
            out, nullptr, DMODEL);
    }
}

// round 17
// speedup vs baseline: 1.0144x; 1.0144x over previous
#include <cuda_runtime.h>
#include <cuda_fp16.h>
#include <math.h>
#include <stdint.h>

// Problem constants
#define BB      4
#define TT      1024
#define DMODEL  2048
#define NHEADS  16
#define HDIM    128
#define MTOK    (BB * TT)        // 4096
#define NQKV    (3 * DMODEL)     // 6144
#define GK      2048

// ---------------------------------------------------------------------------
// Scratch (device globals)
// ---------------------------------------------------------------------------
__device__ __half g_xf[(size_t)MTOK * DMODEL];
__device__ __half g_wqt[(size_t)NQKV * DMODEL];    // w_qkv^T [6144,2048]
__device__ __half g_wot[(size_t)DMODEL * DMODEL];  // w_out^T [2048,2048]
__device__ __half g_qkvf[(size_t)MTOK * NQKV];
__device__ __half g_atf[(size_t)MTOK * DMODEL];

// ---------------------------------------------------------------------------
// PTX helpers (sm_80-class only: legal on plain compute_103)
// ---------------------------------------------------------------------------
__device__ __forceinline__ uint32_t smem_u32(const void* p) {
    uint32_t a;
    asm("{ .reg .u64 t; cvta.to.shared.u64 t, %1; cvt.u32.u64 %0, t; }" : "=r"(a) : "l"(p));
    return a;
}
__device__ __forceinline__ void cp16(uint32_t dst, const void* src) {
    asm volatile("cp.async.cg.shared.global [%0], [%1], 16;"
                 :: "r"(dst), "l"(__cvta_generic_to_global(src)) : "memory");
}
__device__ __forceinline__ void cp_commit() { asm volatile("cp.async.commit_group;" ::: "memory"); }
__device__ __forceinline__ void cp_wait0()  { asm volatile("cp.async.wait_group 0;" ::: "memory"); }
__device__ __forceinline__ void cp_wait1()  { asm volatile("cp.async.wait_group 1;" ::: "memory"); }

__device__ __forceinline__ void ldsm4(uint32_t (&r)[4], uint32_t addr) {
    asm volatile("ldmatrix.sync.aligned.m8n8.x4.shared.b16 {%0,%1,%2,%3}, [%4];"
                 : "=r"(r[0]), "=r"(r[1]), "=r"(r[2]), "=r"(r[3]) : "r"(addr));
}
__device__ __forceinline__ void ldsm4t(uint32_t (&r)[4], uint32_t addr) {
    asm volatile("ldmatrix.sync.aligned.m8n8.x4.trans.shared.b16 {%0,%1,%2,%3}, [%4];"
                 : "=r"(r[0]), "=r"(r[1]), "=r"(r[2]), "=r"(r[3]) : "r"(addr));
}
__device__ __forceinline__ void mma16816(float (&d)[4], const uint32_t (&a)[4],
                                         uint32_t b0, uint32_t b1) {
    asm volatile("mma.sync.aligned.m16n8k16.row.col.f32.f16.f16.f32 "
                 "{%0,%1,%2,%3}, {%4,%5,%6,%7}, {%8,%9}, {%0,%1,%2,%3};"
                 : "+f"(d[0]), "+f"(d[1]), "+f"(d[2]), "+f"(d[3])
                 : "r"(a[0]), "r"(a[1]), "r"(a[2]), "r"(a[3]), "r"(b0), "r"(b1));
}
__device__ __forceinline__ uint32_t pack_h2(float x, float y) {
    __half2 h = __floats2half2_rn(x, y);
    return *reinterpret_cast<uint32_t*>(&h);
}

// ---------------------------------------------------------------------------
// Convert fp32 -> fp16
// ---------------------------------------------------------------------------
__global__ void convert_kernel(const float* __restrict__ in,
                               __half* __restrict__ outp, int n4)
{
    int i = blockIdx.x * blockDim.x + threadIdx.x;
    if (i >= n4) return;
    float4 v = ((const float4*)in)[i];
    uint2 o;
    o.x = pack_h2(v.x, v.y);
    o.y = pack_h2(v.z, v.w);
    ((uint2*)outp)[i] = o;
}

// ---------------------------------------------------------------------------
// Transpose + convert: W [K,N] fp32 -> Wt [N,K] fp16
// ---------------------------------------------------------------------------
__global__ void transpose_convert_kernel(const float* __restrict__ W,
                                         __half* __restrict__ Tt,
                                         int K, int N)
{
    __shared__ float t[32][33];
    const int tx = threadIdx.x, ty = threadIdx.y;
    const int n0 = blockIdx.x * 32, k0 = blockIdx.y * 32;
    #pragma unroll
    for (int i = 0; i < 4; ++i)
        t[ty + 8 * i][tx] = W[(size_t)(k0 + ty + 8 * i) * N + n0 + tx];
    __syncthreads();
    #pragma unroll
    for (int i = 0; i < 4; ++i) {
        float v = t[tx][ty + 8 * i];
        Tt[(size_t)(n0 + ty + 8 * i) * K + k0 + tx] = __float2half_rn(v);
    }
}

// ---------------------------------------------------------------------------
// fp16 GEMM via mma.sync: C[M,N] = A@B^T + bias.  (R15 configuration —
// measured best.)
// CTA 128x128, warp 32x64 (4x2), BK=64, 3-stage cp.async, 2 CTAs/SM.
// ---------------------------------------------------------------------------
#define BKG       64
#define NCHUNK    (GK / BKG)      // 32
#define STAGES    3
#define A_OFF     0               // 128 rows x 128B = 16384
#define B_OFF     16384
#define STAGE_BYTES 32768
#define GSMEM     (STAGES * STAGE_BYTES)   // 98304

__device__ __forceinline__ uint32_t swg(int r, int s) {
    return (uint32_t)(r * 128 + ((s ^ (r & 7)) << 4));
}

__device__ __forceinline__ void load_stage(uint32_t sb, int stage,
                                           const __half* __restrict__ A,
                                           const __half* __restrict__ B,
                                           int brow, int bcol, int k0, int tid)
{
    const uint32_t base = sb + (uint32_t)stage * STAGE_BYTES;
    const int r = tid >> 1;               // 0..127
    const int sbase = (tid & 1) << 2;     // 0 or 4
    const __half* a = A + (size_t)(brow + r) * GK + k0 + sbase * 8;
    const __half* b = B + (size_t)(bcol + r) * GK + k0 + sbase * 8;
    #pragma unroll
    for (int i = 0; i < 4; ++i) {
        const uint32_t o = swg(r, sbase + i);
        cp16(base + A_OFF + o, a + i * 8);
        cp16(base + B_OFF + o, b + i * 8);
    }
    cp_commit();
}

template <bool HALF_OUT>
__global__ __launch_bounds__(256, 2)
void gemm_f16_kernel(const __half* __restrict__ A,
                     const __half* __restrict__ B,
                     const float* __restrict__ bias,
                     float* __restrict__ C,
                     __half* __restrict__ Ch, int N)
{
    extern __shared__ char smem[];
    const uint32_t sb = smem_u32(smem);
    const int tid  = threadIdx.x;
    const int lane = tid & 31;
    const int wid  = tid >> 5;
    const int wm   = wid >> 1;
    const int wn   = wid & 1;
    const int brow = blockIdx.y * 128;
    const int bcol = blockIdx.x * 128;
    const int m0   = wm * 32;
    const int n0   = wn * 64;
    const int kk0  = (wid & 1) << 1;     // phase stagger: 0 or 2

    float acc[2][8][4];
    #pragma unroll
    for (int mt = 0; mt < 2; ++mt)
        #pragma unroll
        for (int nt = 0; nt < 8; ++nt)
            #pragma unroll
            for (int i = 0; i < 4; ++i) acc[mt][nt][i] = 0.0f;

    load_stage(sb, 0, A, B, brow, bcol, 0, tid);
    load_stage(sb, 1, A, B, brow, bcol, BKG, tid);

    #pragma unroll 2
    for (int c = 0; c < NCHUNK; ++c) {
        if (c + 1 < NCHUNK) cp_wait1(); else cp_wait0();
        __syncthreads();
        if (c + 2 < NCHUNK)
            load_stage(sb, (c + 2) % STAGES, A, B, brow, bcol,
                       (c + 2) * BKG, tid);

        const uint32_t st = sb + (uint32_t)(c % STAGES) * STAGE_BYTES;
        #pragma unroll
        for (int kx = 0; kx < 4; ++kx) {     // staggered k16 steps in BK=64
            const int kk = (kx + kk0) & 3;
            uint32_t aF[2][4], bF[4][4];
            const int seg = 2 * kk + (lane >> 4);
            #pragma unroll
            for (int mt = 0; mt < 2; ++mt)
                ldsm4(aF[mt], st + A_OFF + swg(m0 + mt * 16 + (lane & 15), seg));
            #pragma unroll
            for (int p = 0; p < 4; ++p)
                ldsm4(bF[p], st + B_OFF + swg(n0 + p * 16 + (lane & 15), seg));
            #pragma unroll
            for (int mt = 0; mt < 2; ++mt)
                #pragma unroll
                for (int nt = 0; nt < 8; ++nt) {
                    const int p = nt >> 1, sub = nt & 1;
                    mma16816(acc[mt][nt], aF[mt], bF[p][sub], bF[p][sub + 2]);
                }
        }
        // no end-of-chunk barrier: next iteration's top barrier (after
        // cp_wait) orders all reads of this stage before its rewrite.
    }

    #pragma unroll
    for (int mt = 0; mt < 2; ++mt) {
        const int r0 = brow + m0 + mt * 16 + (lane >> 2);
        #pragma unroll
        for (int nt = 0; nt < 8; ++nt) {
            const int col = bcol + n0 + nt * 8 + (lane & 3) * 2;
            const float b0 = bias[col], b1 = bias[col + 1];
            const float v0 = acc[mt][nt][0] + b0, v1 = acc[mt][nt][1] + b1;
            const float v2 = acc[mt][nt][2] + b0, v3 = acc[mt][nt][3] + b1;
            if (HALF_OUT) {
                *(uint32_t*)(Ch + (size_t)r0 * N + col) = pack_h2(v0, v1);
                *(uint32_t*)(Ch + (size_t)(r0 + 8) * N + col) = pack_h2(v2, v3);
            } else {
                *(float2*)(C + (size_t)r0 * N + col) = make_float2(v0, v1);
                *(float2*)(C + (size_t)(r0 + 8) * N + col) = make_float2(v2, v3);
            }
        }
    }
}

// ---------------------------------------------------------------------------
// Flash attention via mma.sync (fp16 single-term), causal — R15 form:
// 2-stage KV ring, depth-1 prefetch, two barriers per iteration (96 KB smem,
// preserving the larger L1 carveout that the 3-stage variant lost).
// ---------------------------------------------------------------------------
#define FBQ   128
#define FBKV  64
#define FQ_O  0
#define FSTG  32768
#define FSTGSZ 32768
#define FK_O  0
#define FV_O  16384
#define FSMEM (FSTG + 2 * FSTGSZ)   // 98304

__device__ __forceinline__ uint32_t swzf(int r, int c) {
    return (uint32_t)(r * 256 + ((c ^ (r & 7)) << 4));
}

__global__ __launch_bounds__(256)
void flash_mma_kernel(const __half* __restrict__ qkvf,
                      __half* __restrict__ of)
{
    extern __shared__ char smem[];
    const uint32_t sb = smem_u32(smem);
    const int tid  = threadIdx.x;
    const int lane = tid & 31;
    const int wid  = tid >> 5;
    const int qb   = blockIdx.x;
    const int bh   = blockIdx.y;
    const int b    = bh >> 4;
    const int h    = bh & 15;
    const int m0   = wid * 16;
    const int tokQ = b * TT + qb * FBQ;
    const float scale = 0.08838834764831845f;

    // stage Q + KV block 0
    {
        #pragma unroll
        for (int i = 0; i < 8; ++i) {
            const int idx = i * 256 + tid;
            const int r = idx >> 4, c = idx & 15;
            cp16(sb + FQ_O + swzf(r, c),
                 qkvf + (size_t)(tokQ + r) * NQKV + h * HDIM + c * 8);
        }
        #pragma unroll
        for (int i = 0; i < 4; ++i) {
            const int idx = i * 256 + tid;
            const int r = idx >> 4, c = idx & 15;
            const uint32_t o = swzf(r, c);
            const size_t gk = (size_t)(b * TT + r) * NQKV + DMODEL + h * HDIM + c * 8;
            cp16(sb + FSTG + FK_O + o, qkvf + gk);
            cp16(sb + FSTG + FV_O + o, qkvf + gk + DMODEL);
        }
    }
    cp_commit();

    const int jmax = 2 * qb + 1;
    float m_[2] = {-1e30f, -1e30f};
    float l_[2] = {0.0f, 0.0f};
    float o_[16][4];
    #pragma unroll
    for (int ng = 0; ng < 16; ++ng)
        #pragma unroll
        for (int i = 0; i < 4; ++i) o_[ng][i] = 0.0f;

    uint32_t qF[8][4];
    const int qrow0 = qb * FBQ + m0 + (lane >> 2);

    for (int j = 0; j <= jmax; ++j) {
        if (j < jmax) {
            const uint32_t stb = sb + FSTG + (uint32_t)((j + 1) & 1) * FSTGSZ;
            #pragma unroll
            for (int i = 0; i < 4; ++i) {
                const int idx = i * 256 + tid;
                const int r = idx >> 4, c = idx & 15;
                const uint32_t o = swzf(r, c);
                const size_t gk = (size_t)(b * TT + (j + 1) * FBKV + r) * NQKV
                                + DMODEL + h * HDIM + c * 8;
                cp16(stb + FK_O + o, qkvf + gk);
                cp16(stb + FV_O + o, qkvf + gk + DMODEL);
            }
        }
        cp_commit();
        if (j < jmax) cp_wait1(); else cp_wait0();
        __syncthreads();

        if (j == 0) {
            #pragma unroll
            for (int kc = 0; kc < 8; ++kc)
                ldsm4(qF[kc], sb + FQ_O + swzf(m0 + (lane & 15), 2 * kc + (lane >> 4)));
        }

        const uint32_t st = sb + FSTG + (uint32_t)(j & 1) * FSTGSZ;

        float s[8][4];
        #pragma unroll
        for (int nt = 0; nt < 8; ++nt)
            #pragma unroll
            for (int i = 0; i < 4; ++i) s[nt][i] = 0.0f;

        #pragma unroll
        for (int kc = 0; kc < 8; ++kc) {
            #pragma unroll
            for (int p = 0; p < 4; ++p) {
                uint32_t kF[4];
                ldsm4(kF, st + FK_O + swzf(p * 16 + (lane & 15), 2 * kc + (lane >> 4)));
                #pragma unroll
                for (int sub = 0; sub < 2; ++sub)
                    mma16816(s[2 * p + sub], qF[kc], kF[sub], kF[sub + 2]);
            }
        }

        #pragma unroll
        for (int nt = 0; nt < 8; ++nt)
            #pragma unroll
            for (int i = 0; i < 4; ++i) s[nt][i] *= scale;
        if (j >= 2 * qb) {
            const int kb = j * FBKV + ((lane & 3) << 1);
            #pragma unroll
            for (int nt = 0; nt < 8; ++nt) {
                const int k0 = kb + nt * 8, k1 = k0 + 1;
                if (k0 > qrow0)     s[nt][0] = -1e30f;
                if (k1 > qrow0)     s[nt][1] = -1e30f;
                if (k0 > qrow0 + 8) s[nt][2] = -1e30f;
                if (k1 > qrow0 + 8) s[nt][3] = -1e30f;
            }
        }

        float mx0 = -1e30f, mx1 = -1e30f;
        #pragma unroll
        for (int nt = 0; nt < 8; ++nt) {
            mx0 = fmaxf(mx0, fmaxf(s[nt][0], s[nt][1]));
            mx1 = fmaxf(mx1, fmaxf(s[nt][2], s[nt][3]));
        }
        mx0 = fmaxf(mx0, __shfl_xor_sync(0xffffffffu, mx0, 1));
        mx0 = fmaxf(mx0, __shfl_xor_sync(0xffffffffu, mx0, 2));
        mx1 = fmaxf(mx1, __shfl_xor_sync(0xffffffffu, mx1, 1));
        mx1 = fmaxf(mx1, __shfl_xor_sync(0xffffffffu, mx1, 2));
        const float mn0 = fmaxf(m_[0], mx0);
        const float mn1 = fmaxf(m_[1], mx1);
        const float a0 = __expf(m_[0] - mn0);
        const float a1 = __expf(m_[1] - mn1);
        float sum0 = 0.0f, sum1 = 0.0f;
        #pragma unroll
        for (int nt = 0; nt < 8; ++nt) {
            s[nt][0] = __expf(s[nt][0] - mn0); sum0 += s[nt][0];
            s[nt][1] = __expf(s[nt][1] - mn0); sum0 += s[nt][1];
            s[nt][2] = __expf(s[nt][2] - mn1); sum1 += s[nt][2];
            s[nt][3] = __expf(s[nt][3] - mn1); sum1 += s[nt][3];
        }
        sum0 += __shfl_xor_sync(0xffffffffu, sum0, 1);
        sum0 += __shfl_xor_sync(0xffffffffu, sum0, 2);
        sum1 += __shfl_xor_sync(0xffffffffu, sum1, 1);
        sum1 += __shfl_xor_sync(0xffffffffu, sum1, 2);
        l_[0] = l_[0] * a0 + sum0;
        l_[1] = l_[1] * a1 + sum1;
        m_[0] = mn0; m_[1] = mn1;
        #pragma unroll
        for (int ng = 0; ng < 16; ++ng) {
            o_[ng][0] *= a0; o_[ng][1] *= a0;
            o_[ng][2] *= a1; o_[ng][3] *= a1;
        }

        // O += P V
        #pragma unroll
        for (int kt = 0; kt < 4; ++kt) {
            uint32_t pF[4];
            pF[0] = pack_h2(s[2 * kt][0],     s[2 * kt][1]);
            pF[1] = pack_h2(s[2 * kt][2],     s[2 * kt][3]);
            pF[2] = pack_h2(s[2 * kt + 1][0], s[2 * kt + 1][1]);
            pF[3] = pack_h2(s[2 * kt + 1][2], s[2 * kt + 1][3]);
            #pragma unroll
            for (int g2 = 0; g2 < 8; ++g2) {
                uint32_t vF[4];
                ldsm4t(vF, st + FV_O + swzf(kt * 16 + (lane & 15), 2 * g2 + (lane >> 4)));
                #pragma unroll
                for (int sub = 0; sub < 2; ++sub)
                    mma16816(o_[2 * g2 + sub], pF, vF[2 * sub], vF[2 * sub + 1]);
            }
        }
        __syncthreads();
    }

    const float inv0 = 1.0f / l_[0];
    const float inv1 = 1.0f / l_[1];
    const size_t tok0 = (size_t)tokQ + m0 + (lane >> 2);
    #pragma unroll
    for (int ng = 0; ng < 16; ++ng) {
        const int col = h * HDIM + ng * 8 + ((lane & 3) << 1);
        *(uint32_t*)(of + tok0 * DMODEL + col) =
            pack_h2(o_[ng][0] * inv0, o_[ng][1] * inv0);
        *(uint32_t*)(of + (tok0 + 8) * DMODEL + col) =
            pack_h2(o_[ng][2] * inv1, o_[ng][3] * inv1);
    }
}

// ---------------------------------------------------------------------------
extern "C" void kernel_launch(void* const* d_in, const int* in_sizes, int n_in,
                              void* d_out, int out_size)
{
    (void)in_sizes; (void)n_in; (void)out_size;
    const float* x      = (const float*)d_in[0];
    const float* w_qkv  = (const float*)d_in[1];
    const float* b_qkv  = (const float*)d_in[2];
    const float* w_out  = (const float*)d_in[3];
    const float* b_out  = (const float*)d_in[4];
    float* out          = (float*)d_out;

    void *xf, *wq, *wo, *qvf, *atf;
    cudaGetSymbolAddress(&xf, g_xf);
    cudaGetSymbolAddress(&wq, g_wqt);
    cudaGetSymbolAddress(&wo, g_wot);
    cudaGetSymbolAddress(&qvf, g_qkvf);
    cudaGetSymbolAddress(&atf, g_atf);

    cudaFuncSetAttribute(gemm_f16_kernel<true>,
                         cudaFuncAttributeMaxDynamicSharedMemorySize, GSMEM);
    cudaFuncSetAttribute(gemm_f16_kernel<false>,
                         cudaFuncAttributeMaxDynamicSharedMemorySize, GSMEM);
    cudaFuncSetAttribute(flash_mma_kernel,
                         cudaFuncAttributeMaxDynamicSharedMemorySize, FSMEM);

    // Side streams + events for prep overlap (created once; capture-fork idiom)
    static cudaStream_t s1 = nullptr, s2 = nullptr;
    static cudaEvent_t eFork = nullptr, eWq = nullptr, eWo = nullptr;
    if (!s1) {
        cudaStreamCreateWithFlags(&s1, cudaStreamNonBlocking);
        cudaStreamCreateWithFlags(&s2, cudaStreamNonBlocking);
        cudaEventCreateWithFlags(&eFork, cudaEventDisableTiming);
        cudaEventCreateWithFlags(&eWq, cudaEventDisableTiming);
        cudaEventCreateWithFlags(&eWo, cudaEventDisableTiming);
    }

    // Fork: s1 (w_qkv transpose) and s2 (w_out transpose) branch off main
    cudaEventRecord(eFork, 0);
    cudaStreamWaitEvent(s1, eFork, 0);
    cudaStreamWaitEvent(s2, eFork, 0);

    {
        dim3 blk(32, 8);
        transpose_convert_kernel<<<dim3(NQKV / 32, DMODEL / 32), blk, 0, s1>>>(
            w_qkv, (__half*)wq, DMODEL, NQKV);
        cudaEventRecord(eWq, s1);
        transpose_convert_kernel<<<dim3(DMODEL / 32, DMODEL / 32), blk, 0, s2>>>(
            w_out, (__half*)wo, DMODEL, DMODEL);
        cudaEventRecord(eWo, s2);
    }
    // Convert x on main stream (overlaps with both transposes)
    {
        const int n4 = MTOK * DMODEL / 4;
        convert_kernel<<<(n4 + 255) / 256, 256>>>(x, (__half*)xf, n4);
    }

    // 1) QKV projection -> fp16 (needs xf + wqt)
    cudaStreamWaitEvent(0, eWq, 0);
    {
        dim3 grid(NQKV / 128, MTOK / 128);
        gemm_f16_kernel<true><<<grid, 256, GSMEM>>>(
            (const __half*)xf, (const __half*)wq, b_qkv,
            nullptr, (__half*)qvf, NQKV);
    }
    // 2) Causal flash attention -> fp16 (w_out transpose overlaps all of this)
    {
        dim3 grid(TT / FBQ, BB * NHEADS);
        flash_mma_kernel<<<grid, 256, FSMEM>>>(
            (const __half*)qvf, (__half*)atf);
    }
    // 3) Output projection -> fp32 out (needs atf + wot)
    cudaStreamWaitEvent(0, eWo, 0);
    {
        dim3 grid(DMODEL / 128, MTOK / 128);
        gemm_f16_kernel<false><<<grid, 256, GSMEM>>>(
            (const __half*)atf, (const __half*)wo, b_out,
            out, nullptr, DMODEL);
    }
}